// round 3
// baseline (speedup 1.0000x reference)
#include <cuda_runtime.h>
#include <cuda_bf16.h>
#include <cstdint>

#define Bb 4
#define Nn 256
#define Ee 256
#define Hh 16
#define Dd 16
#define FFh 512
#define Ll 5
#define BNE (Bb*Nn*Ee)          // 262144
#define BNF (Bb*Nn*FFh)         // 524288

// ---------------- device scratch (no allocations allowed) ----------------
__device__ float g_scaled [Bb*Nn*Nn];
__device__ float g_scaledT[Bb*Nn*Nn];
__device__ float g_mn[Bb], g_mx[Bb];
__device__ float g_alpha[Ll*2*Hh], g_beta[Ll*2*Hh];
__device__ float g_bufA[2*BNE], g_bufB[2*BNE];
__device__ float g_Q[2*BNE], g_K[2*BNE], g_V[2*BNE], g_O[2*BNE];
__device__ float g_t1[2*BNE], g_o1[2*BNE];
__device__ float g_ff[2*BNF];
__device__ float g_P[2*Bb*Hh*Nn*Nn];   // 8.4M floats, softmax probabilities

// ---------------- min/max per batch ----------------
__global__ void k_minmax(const float* __restrict__ data, float* mn, float* mx)
{
    int b = blockIdx.x, tid = threadIdx.x;
    const float* p = data + (size_t)b*Nn*Nn;
    float lmn = 1e30f, lmx = -1e30f;
    for (int i = tid; i < Nn*Nn; i += 256) { float v = p[i]; lmn = fminf(lmn,v); lmx = fmaxf(lmx,v); }
    __shared__ float smn[256], smx[256];
    smn[tid]=lmn; smx[tid]=lmx; __syncthreads();
    for (int s=128; s; s>>=1){ if (tid<s){ smn[tid]=fminf(smn[tid],smn[tid+s]); smx[tid]=fmaxf(smx[tid],smx[tid+s]); } __syncthreads(); }
    if (!tid){ mn[b]=smn[0]; mx[b]=smx[0]; }
}

// ---------------- scaled + transpose ----------------
__global__ void k_scale(const float* __restrict__ data, const float* __restrict__ mn,
                        const float* __restrict__ mx, float* __restrict__ S, float* __restrict__ ST)
{
    int b = blockIdx.z;
    float m0v = mn[b], r = mx[b]-m0v; if (r == 0.f) r = 1.f;
    float inv = 1.f/r;
    __shared__ float tile[32][33];
    int n0 = blockIdx.y*32, mm0 = blockIdx.x*32;
    int tx = threadIdx.x, ty0 = threadIdx.y;
    #pragma unroll
    for (int i=0;i<4;i++){
        int ty = ty0 + i*8;
        float v = (data[((size_t)b*Nn + n0+ty)*Nn + mm0+tx] - m0v)*inv;
        S[((size_t)b*Nn + n0+ty)*Nn + mm0+tx] = v;
        tile[ty][tx] = v;
    }
    __syncthreads();
    #pragma unroll
    for (int i=0;i<4;i++){
        int ty = ty0 + i*8;
        ST[((size_t)b*Nn + mm0+ty)*Nn + n0+tx] = tile[tx][ty];
    }
}

// ---------------- alpha/beta precompute:  alpha[ij,h] = sum_e Wedge[e]*Wmix[ij,e,h] ----------------
__global__ void k_ab(const float* __restrict__ Wedge, const float* __restrict__ bedge,
                     const float* __restrict__ Wmix, float* __restrict__ alpha, float* __restrict__ beta)
{
    int ij = blockIdx.x, h = blockIdx.y, lane = threadIdx.x;
    float a = 0.f, bb = 0.f;
    for (int e = lane; e < Ee; e += 32){
        float wm = Wmix[((size_t)ij*Ee + e)*Hh + h];
        a  += Wedge[e]*wm;
        bb += bedge[e]*wm;
    }
    for (int o=16;o;o>>=1){ a += __shfl_xor_sync(0xffffffffu,a,o); bb += __shfl_xor_sync(0xffffffffu,bb,o); }
    if (!lane){ alpha[ij*Hh+h]=a; beta[ij*Hh+h]=bb; }
}

// ---------------- embedding (rank-1): X[z][b][n][e] = node_rand[b,n]*Wnode[e]+bnode[e] ----------------
__global__ void k_emb(const float* __restrict__ nr, const float* __restrict__ Wn,
                      const float* __restrict__ bn, float* __restrict__ X)
{
    int idx = blockIdx.x*256 + threadIdx.x;   // over B*N*E
    int e = idx & (Ee-1), bni = idx >> 8;
    float v = nr[bni]*Wn[e] + bn[e];
    X[idx] = v;
    X[idx + BNE] = v;
}

// ---------------- generic tiled fp32 GEMM, z-batched (z=0 row block, z=1 col block) ----------------
// C[M,N] = A[M,K] @ W[K,N] (+bias) (+res) (relu?)
__global__ void k_gemm(const float* __restrict__ Abase, int aStrideZ, int aSwap,
                       const float* __restrict__ Wbase, int wStrideZ,
                       const float* __restrict__ biasBase, int biasStrideZ,
                       const float* __restrict__ resBase, int resStrideZ,
                       float* __restrict__ Cbase, int cStrideZ,
                       int M, int N, int K, int doRelu)
{
    int z = blockIdx.z;
    const float* A = Abase + (size_t)(aSwap ? (1-z) : z)*aStrideZ;
    const float* W = Wbase + (size_t)z*wStrideZ;
    const float* bias = biasBase ? biasBase + (size_t)z*biasStrideZ : nullptr;
    const float* res  = resBase  ? resBase  + (size_t)z*resStrideZ  : nullptr;
    float* C = Cbase + (size_t)z*cStrideZ;

    int m0 = blockIdx.y*64, n0 = blockIdx.x*64;
    __shared__ float As[16][64];
    __shared__ float Bs[16][64];
    int tid = threadIdx.x;
    int ty = tid >> 4, tx = tid & 15;
    int ar = tid >> 2, ac = (tid & 3)*4;
    int br = tid >> 4, bc = (tid & 15)*4;
    float acc[4][4] = {};

    for (int k0 = 0; k0 < K; k0 += 16){
        float4 av = *(const float4*)&A[(size_t)(m0+ar)*K + k0 + ac];
        float4 bv = *(const float4*)&W[(size_t)(k0+br)*N + n0 + bc];
        As[ac+0][ar]=av.x; As[ac+1][ar]=av.y; As[ac+2][ar]=av.z; As[ac+3][ar]=av.w;
        *(float4*)&Bs[br][bc] = bv;
        __syncthreads();
        #pragma unroll
        for (int k = 0; k < 16; k++){
            float4 a4 = *(const float4*)&As[k][ty*4];
            float4 b4 = *(const float4*)&Bs[k][tx*4];
            acc[0][0]+=a4.x*b4.x; acc[0][1]+=a4.x*b4.y; acc[0][2]+=a4.x*b4.z; acc[0][3]+=a4.x*b4.w;
            acc[1][0]+=a4.y*b4.x; acc[1][1]+=a4.y*b4.y; acc[1][2]+=a4.y*b4.z; acc[1][3]+=a4.y*b4.w;
            acc[2][0]+=a4.z*b4.x; acc[2][1]+=a4.z*b4.y; acc[2][2]+=a4.z*b4.z; acc[2][3]+=a4.z*b4.w;
            acc[3][0]+=a4.w*b4.x; acc[3][1]+=a4.w*b4.y; acc[3][2]+=a4.w*b4.z; acc[3][3]+=a4.w*b4.w;
        }
        __syncthreads();
    }
    #pragma unroll
    for (int i=0;i<4;i++){
        int m = m0 + ty*4 + i;
        #pragma unroll
        for (int j=0;j<4;j++){
            int n = n0 + tx*4 + j;
            float v = acc[i][j];
            if (bias) v += bias[n];
            if (res)  v += res[(size_t)m*N + n];
            if (doRelu) v = fmaxf(v, 0.f);
            C[(size_t)m*N + n] = v;
        }
    }
}

// ---------------- fused score + edge-bias + softmax -> P ----------------
// grid (rowgroup 8, b*H+h 64, z 2), 256 threads; each thread: 1 row x 32 m
__global__ void k_score(const float* __restrict__ Q, const float* __restrict__ K,
                        const float* __restrict__ scaled, const float* __restrict__ scaledT,
                        const float* __restrict__ alpha, const float* __restrict__ beta,
                        float* __restrict__ P)
{
    int rg = blockIdx.x;
    int bh = blockIdx.y;
    int z  = blockIdx.z;
    int b = bh >> 4, h = bh & 15;
    const float* Sc = z ? scaledT : scaled;
    size_t qkbase = ((size_t)(z*Bb + b))*Nn*Ee;
    const float* Qp = Q + qkbase + (size_t)rg*32*Ee + h*16;
    const float* Kp = K + qkbase + h*16;
    float al = alpha[z*Hh + h], be = beta[z*Hh + h];

    __shared__ float qs[32][17];
    __shared__ float Ks[16][260];
    int tid = threadIdx.x;
    {
        int d = tid & 15, mg = tid >> 4;
        #pragma unroll
        for (int i = 0; i < 16; i++){
            int m = mg + i*16;
            Ks[d][m] = Kp[(size_t)m*Ee + d];
        }
        qs[mg][d]      = Qp[(size_t)mg*Ee + d];
        qs[mg+16][d]   = Qp[(size_t)(mg+16)*Ee + d];
    }
    __syncthreads();

    int n = tid >> 3, s = tid & 7, m0 = s*32;
    const float* srow = Sc + ((size_t)b*Nn + rg*32 + n)*Nn + m0;
    float acc[32];
    #pragma unroll
    for (int mm = 0; mm < 32; mm += 4){
        float4 sv = *(const float4*)&srow[mm];
        acc[mm+0] = sv.x*al + be;
        acc[mm+1] = sv.y*al + be;
        acc[mm+2] = sv.z*al + be;
        acc[mm+3] = sv.w*al + be;
    }
    #pragma unroll
    for (int d = 0; d < 16; d++){
        float qv = qs[n][d] * 0.25f;     // 1/sqrt(D)=0.25 folded in
        #pragma unroll
        for (int mm = 0; mm < 32; mm += 4){
            float4 kv = *(const float4*)&Ks[d][m0+mm];
            acc[mm+0] += qv*kv.x; acc[mm+1] += qv*kv.y;
            acc[mm+2] += qv*kv.z; acc[mm+3] += qv*kv.w;
        }
    }
    float mxv = -1e30f;
    #pragma unroll
    for (int mm=0;mm<32;mm++) mxv = fmaxf(mxv, acc[mm]);
    mxv = fmaxf(mxv, __shfl_xor_sync(0xffffffffu, mxv, 1));
    mxv = fmaxf(mxv, __shfl_xor_sync(0xffffffffu, mxv, 2));
    mxv = fmaxf(mxv, __shfl_xor_sync(0xffffffffu, mxv, 4));
    float sum = 0.f;
    #pragma unroll
    for (int mm=0;mm<32;mm++){ acc[mm] = __expf(acc[mm]-mxv); sum += acc[mm]; }
    sum += __shfl_xor_sync(0xffffffffu, sum, 1);
    sum += __shfl_xor_sync(0xffffffffu, sum, 2);
    sum += __shfl_xor_sync(0xffffffffu, sum, 4);
    float inv = 1.f/sum;
    float* prow = P + (((size_t)(z*Bb+b)*Hh + h)*Nn + rg*32 + n)*Nn + m0;
    #pragma unroll
    for (int mm=0; mm<32; mm+=4){
        float4 o = make_float4(acc[mm]*inv, acc[mm+1]*inv, acc[mm+2]*inv, acc[mm+3]*inv);
        *(float4*)&prow[mm] = o;
    }
}

// ---------------- P @ V -> O ----------------
// grid (ntile 4, b*H+h 64, z 2), 256 threads
__global__ void k_pv(const float* __restrict__ P, const float* __restrict__ V, float* __restrict__ O)
{
    int nt = blockIdx.x;
    int bh = blockIdx.y;
    int z  = blockIdx.z;
    int b = bh >> 4, h = bh & 15;
    size_t vbase = ((size_t)(z*Bb+b))*Nn*Ee + h*16;
    const float* Pp = P + (((size_t)(z*Bb+b)*Hh + h)*Nn + nt*64)*Nn;

    __shared__ float Pm[64][68];
    __shared__ float Vs[64][17];
    int tid = threadIdx.x;
    int d = tid & 15, nl = tid >> 4;
    float acc[4] = {0.f,0.f,0.f,0.f};

    for (int mc = 0; mc < 4; mc++){
        {   // load P tile 64x64
            int r = tid >> 2, c4 = (tid & 3)*16;
            const float* src = Pp + (size_t)r*Nn + mc*64 + c4;
            #pragma unroll
            for (int u=0;u<4;u++){
                float4 v4 = *(const float4*)&src[u*4];
                *(float4*)&Pm[r][c4 + u*4] = v4;
            }
            // load V tile 64x16
            int mg = tid >> 4;
            #pragma unroll
            for (int i=0;i<4;i++){
                int m = mg + i*16;
                Vs[m][d] = V[vbase + (size_t)(mc*64 + m)*Ee + d];
            }
        }
        __syncthreads();
        #pragma unroll 8
        for (int mm = 0; mm < 64; mm++){
            float vv = Vs[mm][d];
            acc[0] += Pm[nl     ][mm]*vv;
            acc[1] += Pm[nl + 16][mm]*vv;
            acc[2] += Pm[nl + 32][mm]*vv;
            acc[3] += Pm[nl + 48][mm]*vv;
        }
        __syncthreads();
    }
    float* Op = O + vbase + (size_t)nt*64*Ee + d;
    #pragma unroll
    for (int i=0;i<4;i++) Op[(size_t)(nl + i*16)*Ee] = acc[i];
}

// ---------------- instance norm over node dim, per (b,e) channel ----------------
// grid (b 4, e/64 4, z 2), 256 threads (64 e x 4 n-chunks)
__global__ void k_inorm(const float* __restrict__ X, float* __restrict__ Y,
                        const float* __restrict__ wbase, const float* __restrict__ bbase)
{
    int z = blockIdx.z, b = blockIdx.x, e0 = blockIdx.y*64;
    const float* w = wbase + (size_t)z*Ee;
    const float* bp = bbase + (size_t)z*Ee;
    int tid = threadIdx.x;
    int el = tid & 63, nc = tid >> 6;
    size_t base = ((size_t)(z*Bb+b))*Nn*Ee;
    float s = 0.f, ss = 0.f;
    for (int n = nc; n < Nn; n += 4){
        float v = X[base + (size_t)n*Ee + e0 + el];
        s += v; ss += v*v;
    }
    __shared__ float sh_s[4][64], sh_ss[4][64];
    __shared__ float muA[64], invA[64];
    sh_s[nc][el] = s; sh_ss[nc][el] = ss;
    __syncthreads();
    if (nc == 0){
        float S  = sh_s[0][el]+sh_s[1][el]+sh_s[2][el]+sh_s[3][el];
        float SS = sh_ss[0][el]+sh_ss[1][el]+sh_ss[2][el]+sh_ss[3][el];
        float mu = S*(1.f/Nn);
        float var = SS*(1.f/Nn) - mu*mu;
        muA[el] = mu;
        invA[el] = rsqrtf(var + 1e-5f);
    }
    __syncthreads();
    float mu = muA[el];
    float sc = invA[el]*w[e0+el];
    float sb = bp[e0+el];
    for (int n = nc; n < Nn; n += 4){
        size_t off = base + (size_t)n*Ee + e0 + el;
        Y[off] = (X[off]-mu)*sc + sb;
    }
}

__global__ void k_copy(float* __restrict__ dst, const float* __restrict__ src, int n)
{
    int i = blockIdx.x*256 + threadIdx.x;
    if (i < n) dst[i] = src[i];
}

// ---------------- host launcher ----------------
extern "C" void kernel_launch(void* const* d_in, const int* in_sizes, int n_in,
                              void* d_out, int out_size)
{
    const float* data      = (const float*)d_in[0];
    const float* node_rand = (const float*)d_in[1];
    const float* Wnode = (const float*)d_in[2];
    const float* bnode = (const float*)d_in[3];
    const float* Wedge = (const float*)d_in[4];
    const float* bedge = (const float*)d_in[5];
    const float* Wq    = (const float*)d_in[6];
    const float* Wk    = (const float*)d_in[7];
    const float* Wv    = (const float*)d_in[8];
    const float* Wcomb = (const float*)d_in[9];
    const float* bcomb = (const float*)d_in[10];
    const float* n1w   = (const float*)d_in[11];
    const float* n1b   = (const float*)d_in[12];
    const float* W1    = (const float*)d_in[13];
    const float* b1    = (const float*)d_in[14];
    const float* W2    = (const float*)d_in[15];
    const float* b2    = (const float*)d_in[16];
    const float* n2w   = (const float*)d_in[17];
    const float* n2b   = (const float*)d_in[18];
    const float* Wmix  = (const float*)d_in[19];

    float *scaled, *scaledT, *mn, *mx, *alpha, *beta;
    float *bufA, *bufB, *Qb, *Kb, *Vb, *Ob, *t1, *o1, *ff, *Pb;
    cudaGetSymbolAddress((void**)&scaled,  g_scaled);
    cudaGetSymbolAddress((void**)&scaledT, g_scaledT);
    cudaGetSymbolAddress((void**)&mn,      g_mn);
    cudaGetSymbolAddress((void**)&mx,      g_mx);
    cudaGetSymbolAddress((void**)&alpha,   g_alpha);
    cudaGetSymbolAddress((void**)&beta,    g_beta);
    cudaGetSymbolAddress((void**)&bufA,    g_bufA);
    cudaGetSymbolAddress((void**)&bufB,    g_bufB);
    cudaGetSymbolAddress((void**)&Qb,      g_Q);
    cudaGetSymbolAddress((void**)&Kb,      g_K);
    cudaGetSymbolAddress((void**)&Vb,      g_V);
    cudaGetSymbolAddress((void**)&Ob,      g_O);
    cudaGetSymbolAddress((void**)&t1,      g_t1);
    cudaGetSymbolAddress((void**)&o1,      g_o1);
    cudaGetSymbolAddress((void**)&ff,      g_ff);
    cudaGetSymbolAddress((void**)&Pb,      g_P);

    k_minmax<<<Bb, 256>>>(data, mn, mx);
    k_scale<<<dim3(8,8,Bb), dim3(32,8)>>>(data, mn, mx, scaled, scaledT);
    k_ab<<<dim3(Ll*2, Hh), 32>>>(Wedge, bedge, Wmix, alpha, beta);
    k_emb<<<BNE/256, 256>>>(node_rand, Wnode, bnode, bufA);

    const int M = Bb*Nn;  // 1024
    for (int i = 0; i < Ll; i++){
        float* Xc = (i & 1) ? bufB : bufA;
        float* Xn = (i & 1) ? bufA : bufB;
        const float* Wq_i    = Wq    + (size_t)i*2*Ee*(Hh*Dd);
        const float* Wk_i    = Wk    + (size_t)i*2*Ee*(Hh*Dd);
        const float* Wv_i    = Wv    + (size_t)i*2*Ee*(Hh*Dd);
        const float* Wcomb_i = Wcomb + (size_t)i*2*(Hh*Dd)*Ee;
        const float* bcomb_i = bcomb + (size_t)i*2*Ee;
        const float* W1_i    = W1    + (size_t)i*2*Ee*FFh;
        const float* b1_i    = b1    + (size_t)i*2*FFh;
        const float* W2_i    = W2    + (size_t)i*2*FFh*Ee;
        const float* b2_i    = b2    + (size_t)i*2*Ee;

        // Q = X[z] @ Wq ;  K,V = X[1-z] @ Wk/Wv
        k_gemm<<<dim3(4,16,2),256>>>(Xc, BNE, 0, Wq_i, Ee*Hh*Dd, nullptr,0, nullptr,0, Qb, BNE, M, 256, 256, 0);
        k_gemm<<<dim3(4,16,2),256>>>(Xc, BNE, 1, Wk_i, Ee*Hh*Dd, nullptr,0, nullptr,0, Kb, BNE, M, 256, 256, 0);
        k_gemm<<<dim3(4,16,2),256>>>(Xc, BNE, 1, Wv_i, Ee*Hh*Dd, nullptr,0, nullptr,0, Vb, BNE, M, 256, 256, 0);
        // softmax( QK^T/4 + scaled*alpha + beta ) -> P
        k_score<<<dim3(8, Bb*Hh, 2), 256>>>(Qb, Kb, scaled, scaledT, alpha + i*2*Hh, beta + i*2*Hh, Pb);
        // O = P @ V
        k_pv<<<dim3(4, Bb*Hh, 2), 256>>>(Pb, Vb, Ob);
        // t1 = O @ Wcomb + bcomb + X[z]
        k_gemm<<<dim3(4,16,2),256>>>(Ob, BNE, 0, Wcomb_i, (Hh*Dd)*Ee, bcomb_i, Ee, Xc, BNE, t1, BNE, M, 256, 256, 0);
        // o1 = instnorm(t1)
        k_inorm<<<dim3(Bb,4,2),256>>>(t1, o1, n1w + (size_t)i*2*Ee, n1b + (size_t)i*2*Ee);
        // ff = relu(o1 @ W1 + b1)
        k_gemm<<<dim3(8,16,2),256>>>(o1, BNE, 0, W1_i, Ee*FFh, b1_i, FFh, nullptr,0, ff, BNF, M, 512, 256, 1);
        // t1 = ff @ W2 + b2 + o1
        k_gemm<<<dim3(4,16,2),256>>>(ff, BNF, 0, W2_i, FFh*Ee, b2_i, Ee, o1, BNE, t1, BNE, M, 256, 512, 0);
        // Xn = instnorm(t1)
        k_inorm<<<dim3(Bb,4,2),256>>>(t1, Xn, n2w + (size_t)i*2*Ee, n2b + (size_t)i*2*Ee);
    }

    // final activations are in bufB (L=5: A->B->A->B->A->B)
    int total = 2*BNE;
    if (out_size < total) total = out_size;
    k_copy<<<(total+255)/256, 256>>>((float*)d_out, bufB, total);
}

// round 6
// speedup vs baseline: 1.2185x; 1.2185x over previous
#include <cuda_runtime.h>
#include <cuda_bf16.h>
#include <cstdint>

#define Bb 4
#define Nn 256
#define Ee 256
#define Hh 16
#define Dd 16
#define FFh 512
#define Ll 5
#define BNE (Bb*Nn*Ee)          // 262144
#define BNF (Bb*Nn*FFh)         // 524288

// ================= device scratch =================
__device__ float g_scaled [Bb*Nn*Nn];
__device__ float g_scaledT[Bb*Nn*Nn];
__device__ float g_mn[Bb], g_mx[Bb];
__device__ float g_alpha[Ll*2*Hh], g_beta[Ll*2*Hh];
__device__ float g_bufA[2*BNE], g_bufB[2*BNE];
__device__ float g_Q[2*BNE], g_K[2*BNE], g_V[2*BNE];
__device__ float g_t1[2*BNE], g_o1[2*BNE];
__device__ float g_P[2*Bb*Hh*Nn*Nn];

// bf16 split activations
__device__ __nv_bfloat16 g_xhA[2*BNE], g_xlA[2*BNE], g_xhB[2*BNE], g_xlB[2*BNE];
__device__ __nv_bfloat16 g_oh[2*BNE],  g_ol[2*BNE];
__device__ __nv_bfloat16 g_o1h[2*BNE], g_o1l[2*BNE];
__device__ __nv_bfloat16 g_ffh[2*BNF], g_ffl[2*BNF];
// bf16 split transposed weights (WT[N,K])
__device__ __nv_bfloat16 g_wqh[10*65536],  g_wql[10*65536];
__device__ __nv_bfloat16 g_wkh[10*65536],  g_wkl[10*65536];
__device__ __nv_bfloat16 g_wvh[10*65536],  g_wvl[10*65536];
__device__ __nv_bfloat16 g_wch[10*65536],  g_wcl[10*65536];
__device__ __nv_bfloat16 g_w1h[10*131072], g_w1l[10*131072];
__device__ __nv_bfloat16 g_w2h[10*131072], g_w2l[10*131072];

// ================= small kernels =================
__global__ void k_minmax(const float* __restrict__ data, float* mn, float* mx)
{
    int b = blockIdx.x, tid = threadIdx.x;
    const float* p = data + (size_t)b*Nn*Nn;
    float lmn = 1e30f, lmx = -1e30f;
    for (int i = tid; i < Nn*Nn; i += 256) { float v = p[i]; lmn = fminf(lmn,v); lmx = fmaxf(lmx,v); }
    __shared__ float smn[256], smx[256];
    smn[tid]=lmn; smx[tid]=lmx; __syncthreads();
    for (int s=128; s; s>>=1){ if (tid<s){ smn[tid]=fminf(smn[tid],smn[tid+s]); smx[tid]=fmaxf(smx[tid],smx[tid+s]); } __syncthreads(); }
    if (!tid){ mn[b]=smn[0]; mx[b]=smx[0]; }
}

__global__ void k_scale(const float* __restrict__ data, const float* __restrict__ mn,
                        const float* __restrict__ mx, float* __restrict__ S, float* __restrict__ ST)
{
    int b = blockIdx.z;
    float m0v = mn[b], r = mx[b]-m0v; if (r == 0.f) r = 1.f;
    float inv = 1.f/r;
    __shared__ float tile[32][33];
    int n0 = blockIdx.y*32, mm0 = blockIdx.x*32;
    int tx = threadIdx.x, ty0 = threadIdx.y;
    #pragma unroll
    for (int i=0;i<4;i++){
        int ty = ty0 + i*8;
        float v = (data[((size_t)b*Nn + n0+ty)*Nn + mm0+tx] - m0v)*inv;
        S[((size_t)b*Nn + n0+ty)*Nn + mm0+tx] = v;
        tile[ty][tx] = v;
    }
    __syncthreads();
    #pragma unroll
    for (int i=0;i<4;i++){
        int ty = ty0 + i*8;
        ST[((size_t)b*Nn + mm0+ty)*Nn + n0+tx] = tile[tx][ty];
    }
}

__global__ void k_ab(const float* __restrict__ Wedge, const float* __restrict__ bedge,
                     const float* __restrict__ Wmix, float* __restrict__ alpha, float* __restrict__ beta)
{
    int ij = blockIdx.x, h = blockIdx.y, lane = threadIdx.x;
    float a = 0.f, bb = 0.f;
    for (int e = lane; e < Ee; e += 32){
        float wm = Wmix[((size_t)ij*Ee + e)*Hh + h];
        a  += Wedge[e]*wm;
        bb += bedge[e]*wm;
    }
    for (int o=16;o;o>>=1){ a += __shfl_xor_sync(0xffffffffu,a,o); bb += __shfl_xor_sync(0xffffffffu,bb,o); }
    if (!lane){ alpha[ij*Hh+h]=a; beta[ij*Hh+h]=bb; }
}

__global__ void k_emb(const float* __restrict__ nr, const float* __restrict__ Wn,
                      const float* __restrict__ bn, float* __restrict__ X,
                      __nv_bfloat16* __restrict__ xh, __nv_bfloat16* __restrict__ xl)
{
    int idx = blockIdx.x*256 + threadIdx.x;
    int e = idx & (Ee-1), bni = idx >> 8;
    float v = nr[bni]*Wn[e] + bn[e];
    X[idx] = v; X[idx + BNE] = v;
    __nv_bfloat16 hi = __float2bfloat16(v);
    __nv_bfloat16 lo = __float2bfloat16(v - __bfloat162float(hi));
    xh[idx]=hi; xh[idx+BNE]=hi;
    xl[idx]=lo; xl[idx+BNE]=lo;
}

// transpose + split: W[K,N] fp32 -> WT_hi/lo[N,K] bf16, grid z = matrix
__global__ void k_tsplit(const float* __restrict__ src, __nv_bfloat16* __restrict__ h,
                         __nv_bfloat16* __restrict__ l, int K, int N)
{
    int mat = blockIdx.z;
    const float* s = src + (size_t)mat*K*N;
    __nv_bfloat16* oh = h + (size_t)mat*K*N;
    __nv_bfloat16* ol = l + (size_t)mat*K*N;
    __shared__ float tile[32][33];
    int n0 = blockIdx.x*32, k0 = blockIdx.y*32;
    int tx = threadIdx.x, ty = threadIdx.y;
    #pragma unroll
    for (int i=0;i<4;i++) tile[ty+i*8][tx] = s[(size_t)(k0+ty+i*8)*N + n0+tx];
    __syncthreads();
    #pragma unroll
    for (int i=0;i<4;i++){
        int n = n0+ty+i*8, k = k0+tx;
        float v = tile[tx][ty+i*8];
        __nv_bfloat16 hi = __float2bfloat16(v);
        oh[(size_t)n*K + k] = hi;
        ol[(size_t)n*K + k] = __float2bfloat16(v - __bfloat162float(hi));
    }
}

// ================= HMMA 3xBF16 GEMM core =================
// C[64,64] tile at (m0,n0): C = A@W, A[M,K] from (ah+al), W as WT[N,K]=(wh+wl)
// 128 threads = 4 warps, warp tile 32x32 (2 m-frags x 4 n-frags of m16n8k16)

#define AS 36   // smem row stride in bf16 (64B data + 8B pad)

__device__ __forceinline__ void hmma(float* c, const uint32_t* a, const uint32_t* b){
    asm volatile("mma.sync.aligned.m16n8k16.row.col.f32.bf16.bf16.f32 "
        "{%0,%1,%2,%3}, {%4,%5,%6,%7}, {%8,%9}, {%0,%1,%2,%3};"
        : "+f"(c[0]), "+f"(c[1]), "+f"(c[2]), "+f"(c[3])
        : "r"(a[0]), "r"(a[1]), "r"(a[2]), "r"(a[3]), "r"(b[0]), "r"(b[1]));
}

__device__ __forceinline__ void tgemm_core(
    const __nv_bfloat16* __restrict__ ah, const __nv_bfloat16* __restrict__ al,
    const __nv_bfloat16* __restrict__ wh, const __nv_bfloat16* __restrict__ wl,
    const float* __restrict__ bias, const float* __restrict__ res,
    float* __restrict__ Cf, __nv_bfloat16* __restrict__ Chi, __nv_bfloat16* __restrict__ Clo,
    int m0, int n0, int Ng, int K, int relu)
{
    __shared__ __nv_bfloat16 sAh[2][64][AS], sAl[2][64][AS];
    __shared__ __nv_bfloat16 sBh[2][64][AS], sBl[2][64][AS];

    int tid = threadIdx.x;
    int lane = tid & 31, w = tid >> 5;
    int wm = (w >> 1)*32, wn = (w & 1)*32;
    int g = lane >> 2, tg = lane & 3;

    float acc[2][4][4];
    #pragma unroll
    for (int mi=0;mi<2;mi++)
        #pragma unroll
        for (int ni=0;ni<4;ni++)
            #pragma unroll
            for (int q=0;q<4;q++) acc[mi][ni][q]=0.f;

    const int nch = K >> 5;            // K chunks of 32
    int lr = tid >> 3, lk = (tid & 7)*4;   // 64 rows x 8 k-quads per 128 threads -> 4 iters

    uint2 rA0[4], rA1[4], rB0[4], rB1[4];
    auto loadRegs = [&](int c){
        #pragma unroll
        for (int it = 0; it < 4; it++){
            int r = lr + it*16;
            size_t aoff = (size_t)(m0 + r)*K + c*32 + lk;
            size_t boff = (size_t)(n0 + r)*K + c*32 + lk;
            rA0[it] = *(const uint2*)(ah + aoff);
            rA1[it] = *(const uint2*)(al + aoff);
            rB0[it] = *(const uint2*)(wh + boff);
            rB1[it] = *(const uint2*)(wl + boff);
        }
    };
    auto storeSmem = [&](int st){
        #pragma unroll
        for (int it = 0; it < 4; it++){
            int r = lr + it*16;
            *(uint2*)&sAh[st][r][lk] = rA0[it];
            *(uint2*)&sAl[st][r][lk] = rA1[it];
            *(uint2*)&sBh[st][r][lk] = rB0[it];
            *(uint2*)&sBl[st][r][lk] = rB1[it];
        }
    };

    loadRegs(0);
    storeSmem(0);
    __syncthreads();

    for (int c = 0; c < nch; c++){
        if (c + 1 < nch) loadRegs(c + 1);
        int st = c & 1;
        #pragma unroll
        for (int ks = 0; ks < 2; ks++){
            int kb = ks*16 + 2*tg;
            uint32_t fah[2][4], fal[2][4];
            #pragma unroll
            for (int mi = 0; mi < 2; mi++){
                int rb = wm + mi*16 + g;
                fah[mi][0] = *(const uint32_t*)&sAh[st][rb  ][kb];
                fah[mi][1] = *(const uint32_t*)&sAh[st][rb+8][kb];
                fah[mi][2] = *(const uint32_t*)&sAh[st][rb  ][kb+8];
                fah[mi][3] = *(const uint32_t*)&sAh[st][rb+8][kb+8];
                fal[mi][0] = *(const uint32_t*)&sAl[st][rb  ][kb];
                fal[mi][1] = *(const uint32_t*)&sAl[st][rb+8][kb];
                fal[mi][2] = *(const uint32_t*)&sAl[st][rb  ][kb+8];
                fal[mi][3] = *(const uint32_t*)&sAl[st][rb+8][kb+8];
            }
            uint32_t fbh[4][2], fbl[4][2];
            #pragma unroll
            for (int ni = 0; ni < 4; ni++){
                int nb = wn + ni*8 + g;
                fbh[ni][0] = *(const uint32_t*)&sBh[st][nb][kb];
                fbh[ni][1] = *(const uint32_t*)&sBh[st][nb][kb+8];
                fbl[ni][0] = *(const uint32_t*)&sBl[st][nb][kb];
                fbl[ni][1] = *(const uint32_t*)&sBl[st][nb][kb+8];
            }
            #pragma unroll
            for (int mi = 0; mi < 2; mi++)
                #pragma unroll
                for (int ni = 0; ni < 4; ni++){
                    hmma(acc[mi][ni], fah[mi], fbh[ni]);
                    hmma(acc[mi][ni], fah[mi], fbl[ni]);
                    hmma(acc[mi][ni], fal[mi], fbh[ni]);
                }
        }
        __syncthreads();
        if (c + 1 < nch){
            storeSmem((c + 1) & 1);
            __syncthreads();
        }
    }

    // epilogue
    #pragma unroll
    for (int mi = 0; mi < 2; mi++){
        #pragma unroll
        for (int ni = 0; ni < 4; ni++){
            int col = n0 + wn + ni*8 + 2*tg;
            float b0 = bias ? bias[col]   : 0.f;
            float b1 = bias ? bias[col+1] : 0.f;
            #pragma unroll
            for (int half = 0; half < 2; half++){
                int m = m0 + wm + mi*16 + g + half*8;
                float v0 = acc[mi][ni][half*2+0] + b0;
                float v1 = acc[mi][ni][half*2+1] + b1;
                if (res){
                    v0 += res[(size_t)m*Ng + col];
                    v1 += res[(size_t)m*Ng + col+1];
                }
                if (relu){ v0 = fmaxf(v0, 0.f); v1 = fmaxf(v1, 0.f); }
                if (Cf){
                    float2 o; o.x = v0; o.y = v1;
                    *(float2*)&Cf[(size_t)m*Ng + col] = o;
                }
                if (Chi){
                    __nv_bfloat16 h0 = __float2bfloat16(v0), h1 = __float2bfloat16(v1);
                    __nv_bfloat162 hp; hp.x = h0; hp.y = h1;
                    __nv_bfloat162 lp;
                    lp.x = __float2bfloat16(v0 - __bfloat162float(h0));
                    lp.y = __float2bfloat16(v1 - __bfloat162float(h1));
                    *(__nv_bfloat162*)&Chi[(size_t)m*Ng + col] = hp;
                    *(__nv_bfloat162*)&Clo[(size_t)m*Ng + col] = lp;
                }
            }
        }
    }
}

// fused QKV: grid (12, 16, 2): wsel = x>>2 (0=Q,1=K,2=V), nt = x&3
__global__ void __launch_bounds__(128) k_tqkv(
                       const __nv_bfloat16* __restrict__ xh, const __nv_bfloat16* __restrict__ xl,
                       const __nv_bfloat16* wqh, const __nv_bfloat16* wql,
                       const __nv_bfloat16* wkh, const __nv_bfloat16* wkl,
                       const __nv_bfloat16* wvh, const __nv_bfloat16* wvl,
                       float* Q, float* K, float* V)
{
    int wsel = blockIdx.x >> 2, nt = blockIdx.x & 3, z = blockIdx.z;
    int az = wsel ? (1 - z) : z;
    const __nv_bfloat16 *wh, *wl; float* out;
    if (wsel == 0){ wh = wqh; wl = wql; out = Q; }
    else if (wsel == 1){ wh = wkh; wl = wkl; out = K; }
    else { wh = wvh; wl = wvl; out = V; }
    tgemm_core(xh + (size_t)az*BNE, xl + (size_t)az*BNE,
               wh + (size_t)z*65536, wl + (size_t)z*65536,
               nullptr, nullptr,
               out + (size_t)z*BNE, nullptr, nullptr,
               blockIdx.y*64, nt*64, 256, 256, 0);
}

// generic: grid (Ng/64, 16, 2)
__global__ void __launch_bounds__(128) k_tgemm(
                        const __nv_bfloat16* __restrict__ ah, const __nv_bfloat16* __restrict__ al, int aStrideZ,
                        const __nv_bfloat16* __restrict__ wh, const __nv_bfloat16* __restrict__ wl, int wStrideZ,
                        const float* bias, int biasStrideZ,
                        const float* res, int resStrideZ,
                        float* Cf, __nv_bfloat16* Chi, __nv_bfloat16* Clo, int cStrideZ,
                        int Ng, int K, int relu)
{
    int z = blockIdx.z;
    tgemm_core(ah + (size_t)z*aStrideZ, al + (size_t)z*aStrideZ,
               wh + (size_t)z*wStrideZ, wl + (size_t)z*wStrideZ,
               bias ? bias + (size_t)z*biasStrideZ : nullptr,
               res  ? res  + (size_t)z*resStrideZ  : nullptr,
               Cf  ? Cf  + (size_t)z*cStrideZ : nullptr,
               Chi ? Chi + (size_t)z*cStrideZ : nullptr,
               Clo ? Clo + (size_t)z*cStrideZ : nullptr,
               blockIdx.y*64, blockIdx.x*64, Ng, K, relu);
}

// ================= attention =================
__global__ void k_score(const float* __restrict__ Q, const float* __restrict__ K,
                        const float* __restrict__ scaled, const float* __restrict__ scaledT,
                        const float* __restrict__ alpha, const float* __restrict__ beta,
                        float* __restrict__ P)
{
    int rg = blockIdx.x;
    int bh = blockIdx.y;
    int z  = blockIdx.z;
    int b = bh >> 4, h = bh & 15;
    const float* Sc = z ? scaledT : scaled;
    size_t qkbase = ((size_t)(z*Bb + b))*Nn*Ee;
    const float* Qp = Q + qkbase + (size_t)rg*32*Ee + h*16;
    const float* Kp = K + qkbase + h*16;
    float al = alpha[z*Hh + h], be = beta[z*Hh + h];

    __shared__ float qs[32][17];
    __shared__ float Ks[16][260];
    int tid = threadIdx.x;
    {
        int d = tid & 15, mg = tid >> 4;
        #pragma unroll
        for (int i = 0; i < 16; i++){
            int m = mg + i*16;
            Ks[d][m] = Kp[(size_t)m*Ee + d];
        }
        qs[mg][d]      = Qp[(size_t)mg*Ee + d];
        qs[mg+16][d]   = Qp[(size_t)(mg+16)*Ee + d];
    }
    __syncthreads();

    int n = tid >> 3, s = tid & 7, m0 = s*32;
    const float* srow = Sc + ((size_t)b*Nn + rg*32 + n)*Nn + m0;
    float acc[32];
    #pragma unroll
    for (int mm = 0; mm < 32; mm += 4){
        float4 sv = *(const float4*)&srow[mm];
        acc[mm+0] = sv.x*al + be;
        acc[mm+1] = sv.y*al + be;
        acc[mm+2] = sv.z*al + be;
        acc[mm+3] = sv.w*al + be;
    }
    #pragma unroll
    for (int d = 0; d < 16; d++){
        float qv = qs[n][d] * 0.25f;
        #pragma unroll
        for (int mm = 0; mm < 32; mm += 4){
            float4 kv = *(const float4*)&Ks[d][m0+mm];
            acc[mm+0] += qv*kv.x; acc[mm+1] += qv*kv.y;
            acc[mm+2] += qv*kv.z; acc[mm+3] += qv*kv.w;
        }
    }
    float mxv = -1e30f;
    #pragma unroll
    for (int mm=0;mm<32;mm++) mxv = fmaxf(mxv, acc[mm]);
    mxv = fmaxf(mxv, __shfl_xor_sync(0xffffffffu, mxv, 1));
    mxv = fmaxf(mxv, __shfl_xor_sync(0xffffffffu, mxv, 2));
    mxv = fmaxf(mxv, __shfl_xor_sync(0xffffffffu, mxv, 4));
    float sum = 0.f;
    #pragma unroll
    for (int mm=0;mm<32;mm++){ acc[mm] = __expf(acc[mm]-mxv); sum += acc[mm]; }
    sum += __shfl_xor_sync(0xffffffffu, sum, 1);
    sum += __shfl_xor_sync(0xffffffffu, sum, 2);
    sum += __shfl_xor_sync(0xffffffffu, sum, 4);
    float inv = 1.f/sum;
    float* prow = P + (((size_t)(z*Bb+b)*Hh + h)*Nn + rg*32 + n)*Nn + m0;
    #pragma unroll
    for (int mm=0; mm<32; mm+=4){
        float4 o = make_float4(acc[mm]*inv, acc[mm+1]*inv, acc[mm+2]*inv, acc[mm+3]*inv);
        *(float4*)&prow[mm] = o;
    }
}

// P @ V -> O (bf16 hi/lo split out, consumed by comb tensor GEMM)
__global__ void k_pv(const float* __restrict__ P, const float* __restrict__ V,
                     __nv_bfloat16* __restrict__ Oh, __nv_bfloat16* __restrict__ Ol)
{
    int nt = blockIdx.x;
    int bh = blockIdx.y;
    int z  = blockIdx.z;
    int b = bh >> 4, h = bh & 15;
    size_t vbase = ((size_t)(z*Bb+b))*Nn*Ee + h*16;
    const float* Pp = P + (((size_t)(z*Bb+b)*Hh + h)*Nn + nt*64)*Nn;

    __shared__ float Pm[64][68];
    __shared__ float Vs[64][17];
    int tid = threadIdx.x;
    int d = tid & 15, nl = tid >> 4;
    float acc[4] = {0.f,0.f,0.f,0.f};

    for (int mc = 0; mc < 4; mc++){
        {
            int r = tid >> 2, c4 = (tid & 3)*16;
            const float* src = Pp + (size_t)r*Nn + mc*64 + c4;
            #pragma unroll
            for (int u=0;u<4;u++){
                float4 v4 = *(const float4*)&src[u*4];
                *(float4*)&Pm[r][c4 + u*4] = v4;
            }
            int mg = tid >> 4;
            #pragma unroll
            for (int i=0;i<4;i++){
                int m = mg + i*16;
                Vs[m][d] = V[vbase + (size_t)(mc*64 + m)*Ee + d];
            }
        }
        __syncthreads();
        #pragma unroll 8
        for (int mm = 0; mm < 64; mm++){
            float vv = Vs[mm][d];
            acc[0] += Pm[nl     ][mm]*vv;
            acc[1] += Pm[nl + 16][mm]*vv;
            acc[2] += Pm[nl + 32][mm]*vv;
            acc[3] += Pm[nl + 48][mm]*vv;
        }
        __syncthreads();
    }
    #pragma unroll
    for (int i=0;i<4;i++){
        float v = acc[i];
        __nv_bfloat16 hi = __float2bfloat16(v);
        size_t off = vbase + (size_t)(nt*64 + nl + i*16)*Ee + d;
        Oh[off] = hi;
        Ol[off] = __float2bfloat16(v - __bfloat162float(hi));
    }
}

// instance norm + bf16 split output
__global__ void k_inorm(const float* __restrict__ X, float* __restrict__ Y,
                        const float* __restrict__ wbase, const float* __restrict__ bbase,
                        __nv_bfloat16* __restrict__ Yh, __nv_bfloat16* __restrict__ Yl)
{
    int z = blockIdx.z, b = blockIdx.x, e0 = blockIdx.y*64;
    const float* w = wbase + (size_t)z*Ee;
    const float* bp = bbase + (size_t)z*Ee;
    int tid = threadIdx.x;
    int el = tid & 63, nc = tid >> 6;
    size_t base = ((size_t)(z*Bb+b))*Nn*Ee;
    float s = 0.f, ss = 0.f;
    for (int n = nc; n < Nn; n += 4){
        float v = X[base + (size_t)n*Ee + e0 + el];
        s += v; ss += v*v;
    }
    __shared__ float sh_s[4][64], sh_ss[4][64];
    __shared__ float muA[64], invA[64];
    sh_s[nc][el] = s; sh_ss[nc][el] = ss;
    __syncthreads();
    if (nc == 0){
        float S  = sh_s[0][el]+sh_s[1][el]+sh_s[2][el]+sh_s[3][el];
        float SS = sh_ss[0][el]+sh_ss[1][el]+sh_ss[2][el]+sh_ss[3][el];
        float mu = S*(1.f/Nn);
        float var = SS*(1.f/Nn) - mu*mu;
        muA[el] = mu;
        invA[el] = rsqrtf(var + 1e-5f);
    }
    __syncthreads();
    float mu = muA[el];
    float sc = invA[el]*w[e0+el];
    float sb = bp[e0+el];
    for (int n = nc; n < Nn; n += 4){
        size_t off = base + (size_t)n*Ee + e0 + el;
        float y = (X[off]-mu)*sc + sb;
        Y[off] = y;
        __nv_bfloat16 hi = __float2bfloat16(y);
        Yh[off] = hi;
        Yl[off] = __float2bfloat16(y - __bfloat162float(hi));
    }
}

__global__ void k_copy(float* __restrict__ dst, const float* __restrict__ src, int n)
{
    int i = blockIdx.x*256 + threadIdx.x;
    if (i < n) dst[i] = src[i];
}

// ================= host launcher =================
extern "C" void kernel_launch(void* const* d_in, const int* in_sizes, int n_in,
                              void* d_out, int out_size)
{
    const float* data      = (const float*)d_in[0];
    const float* node_rand = (const float*)d_in[1];
    const float* Wnode = (const float*)d_in[2];
    const float* bnode = (const float*)d_in[3];
    const float* Wedge = (const float*)d_in[4];
    const float* bedge = (const float*)d_in[5];
    const float* Wq    = (const float*)d_in[6];
    const float* Wk    = (const float*)d_in[7];
    const float* Wv    = (const float*)d_in[8];
    const float* Wcomb = (const float*)d_in[9];
    const float* bcomb = (const float*)d_in[10];
    const float* n1w   = (const float*)d_in[11];
    const float* n1b   = (const float*)d_in[12];
    const float* W1    = (const float*)d_in[13];
    const float* b1    = (const float*)d_in[14];
    const float* W2    = (const float*)d_in[15];
    const float* b2    = (const float*)d_in[16];
    const float* n2w   = (const float*)d_in[17];
    const float* n2b   = (const float*)d_in[18];
    const float* Wmix  = (const float*)d_in[19];

    float *scaled, *scaledT, *mn, *mx, *alpha, *beta;
    float *bufA, *bufB, *Qb, *Kb, *Vb, *t1, *o1, *Pb;
    __nv_bfloat16 *xhA,*xlA,*xhB,*xlB,*oh,*ol,*o1h,*o1l,*ffh,*ffl;
    __nv_bfloat16 *wqh,*wql,*wkh,*wkl,*wvh,*wvl,*wch,*wcl,*w1h,*w1l,*w2h,*w2l;
    cudaGetSymbolAddress((void**)&scaled,  g_scaled);
    cudaGetSymbolAddress((void**)&scaledT, g_scaledT);
    cudaGetSymbolAddress((void**)&mn,      g_mn);
    cudaGetSymbolAddress((void**)&mx,      g_mx);
    cudaGetSymbolAddress((void**)&alpha,   g_alpha);
    cudaGetSymbolAddress((void**)&beta,    g_beta);
    cudaGetSymbolAddress((void**)&bufA,    g_bufA);
    cudaGetSymbolAddress((void**)&bufB,    g_bufB);
    cudaGetSymbolAddress((void**)&Qb,      g_Q);
    cudaGetSymbolAddress((void**)&Kb,      g_K);
    cudaGetSymbolAddress((void**)&Vb,      g_V);
    cudaGetSymbolAddress((void**)&t1,      g_t1);
    cudaGetSymbolAddress((void**)&o1,      g_o1);
    cudaGetSymbolAddress((void**)&Pb,      g_P);
    cudaGetSymbolAddress((void**)&xhA, g_xhA); cudaGetSymbolAddress((void**)&xlA, g_xlA);
    cudaGetSymbolAddress((void**)&xhB, g_xhB); cudaGetSymbolAddress((void**)&xlB, g_xlB);
    cudaGetSymbolAddress((void**)&oh,  g_oh);  cudaGetSymbolAddress((void**)&ol,  g_ol);
    cudaGetSymbolAddress((void**)&o1h, g_o1h); cudaGetSymbolAddress((void**)&o1l, g_o1l);
    cudaGetSymbolAddress((void**)&ffh, g_ffh); cudaGetSymbolAddress((void**)&ffl, g_ffl);
    cudaGetSymbolAddress((void**)&wqh, g_wqh); cudaGetSymbolAddress((void**)&wql, g_wql);
    cudaGetSymbolAddress((void**)&wkh, g_wkh); cudaGetSymbolAddress((void**)&wkl, g_wkl);
    cudaGetSymbolAddress((void**)&wvh, g_wvh); cudaGetSymbolAddress((void**)&wvl, g_wvl);
    cudaGetSymbolAddress((void**)&wch, g_wch); cudaGetSymbolAddress((void**)&wcl, g_wcl);
    cudaGetSymbolAddress((void**)&w1h, g_w1h); cudaGetSymbolAddress((void**)&w1l, g_w1l);
    cudaGetSymbolAddress((void**)&w2h, g_w2h); cudaGetSymbolAddress((void**)&w2l, g_w2l);

    // setup
    k_minmax<<<Bb, 256>>>(data, mn, mx);
    k_scale<<<dim3(8,8,Bb), dim3(32,8)>>>(data, mn, mx, scaled, scaledT);
    k_ab<<<dim3(Ll*2, Hh), 32>>>(Wedge, bedge, Wmix, alpha, beta);
    k_emb<<<BNE/256, 256>>>(node_rand, Wnode, bnode, bufA, xhA, xlA);
    // weight transpose+split (10 matrices each)
    k_tsplit<<<dim3(8,8,10),  dim3(32,8)>>>(Wq,    wqh, wql, 256, 256);
    k_tsplit<<<dim3(8,8,10),  dim3(32,8)>>>(Wk,    wkh, wkl, 256, 256);
    k_tsplit<<<dim3(8,8,10),  dim3(32,8)>>>(Wv,    wvh, wvl, 256, 256);
    k_tsplit<<<dim3(8,8,10),  dim3(32,8)>>>(Wcomb, wch, wcl, 256, 256);
    k_tsplit<<<dim3(16,8,10), dim3(32,8)>>>(W1,    w1h, w1l, 256, 512);
    k_tsplit<<<dim3(8,16,10), dim3(32,8)>>>(W2,    w2h, w2l, 512, 256);

    for (int i = 0; i < Ll; i++){
        float* Xc = (i & 1) ? bufB : bufA;
        __nv_bfloat16* xhc = (i & 1) ? xhB : xhA;
        __nv_bfloat16* xlc = (i & 1) ? xlB : xlA;
        __nv_bfloat16* xhn = (i & 1) ? xhA : xhB;
        __nv_bfloat16* xln = (i & 1) ? xlA : xlB;
        float* Xn = (i & 1) ? bufA : bufB;
        size_t w256 = (size_t)i*2*65536;
        size_t w512 = (size_t)i*2*131072;
        const float* bcomb_i = bcomb + (size_t)i*2*Ee;
        const float* b1_i    = b1    + (size_t)i*2*FFh;
        const float* b2_i    = b2    + (size_t)i*2*Ee;

        // Q/K/V tensor GEMMs (fused launch)
        k_tqkv<<<dim3(12,16,2), 128>>>(xhc, xlc,
            wqh + w256, wql + w256, wkh + w256, wkl + w256, wvh + w256, wvl + w256,
            Qb, Kb, Vb);
        // attention
        k_score<<<dim3(8, Bb*Hh, 2), 256>>>(Qb, Kb, scaled, scaledT,
            alpha + i*2*Hh, beta + i*2*Hh, Pb);
        k_pv<<<dim3(4, Bb*Hh, 2), 256>>>(Pb, Vb, oh, ol);
        // t1 = O @ Wcomb + bcomb + Xc
        k_tgemm<<<dim3(4,16,2), 128>>>(oh, ol, BNE, wch + w256, wcl + w256, 65536,
            bcomb_i, Ee, Xc, BNE, t1, nullptr, nullptr, BNE, 256, 256, 0);
        k_inorm<<<dim3(Bb,4,2), 256>>>(t1, o1, n1w + (size_t)i*2*Ee, n1b + (size_t)i*2*Ee, o1h, o1l);
        // ff = relu(o1 @ W1 + b1)  -> bf16 split only
        k_tgemm<<<dim3(8,16,2), 128>>>(o1h, o1l, BNE, w1h + w512, w1l + w512, 131072,
            b1_i, FFh, nullptr, 0, nullptr, ffh, ffl, BNF, 512, 256, 1);
        // t1 = ff @ W2 + b2 + o1
        k_tgemm<<<dim3(4,16,2), 128>>>(ffh, ffl, BNF, w2h + w512, w2l + w512, 131072,
            b2_i, Ee, o1, BNE, t1, nullptr, nullptr, BNE, 256, 512, 0);
        k_inorm<<<dim3(Bb,4,2), 256>>>(t1, Xn, n2w + (size_t)i*2*Ee, n2b + (size_t)i*2*Ee, xhn, xln);
    }

    int total = 2*BNE;
    if (out_size < total) total = out_size;
    k_copy<<<(total+255)/256, 256>>>((float*)d_out, bufB, total);
}